// round 1
// baseline (speedup 1.0000x reference)
#include <cuda_runtime.h>
#include <math.h>

// Problem constants
// target: (8, 3, 128, 128)       = 393216 floats
// output: (8, 16, 3, 128, 128)   = 6291456 floats
// out: scalar float
//
// crps(pred(B,M,C,G), tgt(B,C,G)) = S1/(B*M*C*G) - (1-eps)*S2p/((M-1)*B*M*C*G)
//   S1  = sum |p_m - t|, S2p = sum_{i<j} |p_i - p_j|, eps = 0.05/M
// Spectral term: rfft2 low-pass mask keeps bins (kh<32, kw<16); masked-out bins
// contribute exactly 0 to both sums but the means divide by Gf = 128*65 = 8320.

#define NIMG_OUT 384      // B*M*C
#define NIMG_TGT 24       // B*C
#define NBINS    512      // 32*16 active bins

__device__ double g_acc[4];                 // S1, S2p, S1f, S2fp
__device__ float  g_magM[NIMG_OUT * NBINS];
__device__ float  g_magT[NIMG_TGT * NBINS];

__global__ void k_zero() {
    if (threadIdx.x < 4) g_acc[threadIdx.x] = 0.0;
}

__device__ __forceinline__ void reduce_and_add(float s1, float s2, int accIdx) {
    #pragma unroll
    for (int o = 16; o > 0; o >>= 1) {
        s1 += __shfl_down_sync(0xffffffffu, s1, o);
        s2 += __shfl_down_sync(0xffffffffu, s2, o);
    }
    __shared__ float sh1[8], sh2[8];
    int lane = threadIdx.x & 31, wid = threadIdx.x >> 5;
    if (lane == 0) { sh1[wid] = s1; sh2[wid] = s2; }
    __syncthreads();
    if (wid == 0) {
        int nw = blockDim.x >> 5;
        s1 = (lane < nw) ? sh1[lane] : 0.f;
        s2 = (lane < nw) ? sh2[lane] : 0.f;
        #pragma unroll
        for (int o = 4; o > 0; o >>= 1) {
            s1 += __shfl_down_sync(0xffffffffu, s1, o);
            s2 += __shfl_down_sync(0xffffffffu, s2, o);
        }
        if (lane == 0) {
            atomicAdd(&g_acc[accIdx],     (double)s1);
            atomicAdd(&g_acc[accIdx + 1], (double)s2);
        }
    }
}

// Unified CRPS partial-sum kernel.
// pred layout: pred[b*16*CG + m*CG + r], tgt layout: tgt[b*CG + r], idx = b*CG + r.
// accIdx==2 selects the on-device magnitude scratch (frequency branch).
__global__ void k_crps(const float* __restrict__ pred, const float* __restrict__ tgt,
                       int CG, int total, int accIdx) {
    if (accIdx == 2) { pred = g_magM; tgt = g_magT; }
    int idx = blockIdx.x * blockDim.x + threadIdx.x;
    float s1 = 0.f, s2 = 0.f;
    if (idx < total) {
        int b = idx / CG;
        int r = idx - b * CG;
        float t = tgt[idx];
        const float* base = pred + (size_t)b * 16 * CG + r;
        float p[16];
        #pragma unroll
        for (int m = 0; m < 16; m++) p[m] = base[(size_t)m * CG];
        #pragma unroll
        for (int i = 0; i < 16; i++) {
            s1 += fabsf(p[i] - t);
            #pragma unroll
            for (int j = i + 1; j < 16; j++) s2 += fabsf(p[i] - p[j]);
        }
    }
    reduce_and_add(s1, s2, accIdx);
}

// Pruned 2D DFT: per image compute X[kh,kw] for kh<32, kw<16 and store |X|.
// Stage 1: Y[h][kw] = sum_w x[h][w] * exp(-2pi i kw w / 128)   (real input)
// Stage 2: Z[kh][kw] = sum_h Y[h][kw] * exp(-2pi i kh h / 128)
// Blocks 0..383 -> output images, 384..407 -> target images.
__global__ void k_fft(const float* __restrict__ outp, const float* __restrict__ tgt) {
    int img = blockIdx.x;
    const float* src;
    float* dst;
    if (img < NIMG_OUT) { src = outp + (size_t)img * 16384;              dst = g_magM + img * NBINS; }
    else                { src = tgt  + (size_t)(img - NIMG_OUT) * 16384; dst = g_magT + (img - NIMG_OUT) * NBINS; }

    int tid = threadIdx.x;
    __shared__ float  sx[32 * 129];     // 32-row chunk, padded (conflict-free column walk)
    __shared__ float2 sy[128 * 16];     // stage-1 output (complex)
    __shared__ float2 stw[128];         // twiddle LUT exp(-2pi i j/128)

    if (tid < 128) {
        float s, c;
        sincosf(-6.283185307179586f * (float)tid / 128.0f, &s, &c);
        stw[tid] = make_float2(c, s);
    }

    int warp = tid >> 5, lane = tid & 31;
    int hl  = lane;        // row within 32-row chunk
    int kw0 = warp * 2;    // each warp handles 2 kw bins across all 32 rows

    #pragma unroll
    for (int chunk = 0; chunk < 4; chunk++) {
        __syncthreads();   // stw ready (iter 0) / sx consumed (iters 1+)
        for (int i = tid; i < 4096; i += 256)
            sx[(i >> 7) * 129 + (i & 127)] = src[chunk * 4096 + i];
        __syncthreads();

        int h = chunk * 32 + hl;
        float ar = 0.f, ai = 0.f, br = 0.f, bi = 0.f;
        #pragma unroll 8
        for (int w = 0; w < 128; w++) {
            float  x  = sx[hl * 129 + w];
            float2 t0 = stw[(kw0 * w) & 127];          // warp-uniform -> LDS broadcast
            float2 t1 = stw[((kw0 + 1) * w) & 127];
            ar = fmaf(x, t0.x, ar); ai = fmaf(x, t0.y, ai);
            br = fmaf(x, t1.x, br); bi = fmaf(x, t1.y, bi);
        }
        sy[h * 16 + kw0]     = make_float2(ar, ai);
        sy[h * 16 + kw0 + 1] = make_float2(br, bi);
    }
    __syncthreads();

    // Stage 2: thread -> (kw = tid&15, kh in {tid>>4, tid>>4 + 16}); shares Y loads.
    int kw  = tid & 15;
    int kh0 = tid >> 4;
    int kh1 = kh0 + 16;
    float z0r = 0.f, z0i = 0.f, z1r = 0.f, z1i = 0.f;
    #pragma unroll 4
    for (int h = 0; h < 128; h++) {
        float2 y  = sy[h * 16 + kw];
        float2 t0 = stw[(kh0 * h) & 127];
        float2 t1 = stw[(kh1 * h) & 127];
        z0r = fmaf(y.x, t0.x, fmaf(-y.y, t0.y, z0r));
        z0i = fmaf(y.x, t0.y, fmaf( y.y, t0.x, z0i));
        z1r = fmaf(y.x, t1.x, fmaf(-y.y, t1.y, z1r));
        z1i = fmaf(y.x, t1.y, fmaf( y.y, t1.x, z1i));
    }
    dst[kh0 * 16 + kw] = sqrtf(z0r * z0r + z0i * z0i);
    dst[kh1 * 16 + kw] = sqrtf(z1r * z1r + z1i * z1i);
}

__global__ void k_final(float* out) {
    double S1 = g_acc[0], S2p = g_acc[1], S1f = g_acc[2], S2fp = g_acc[3];
    const double eps = 0.05 / 16.0;
    const double Np  = 8.0 * 16.0 * 3.0 * 16384.0;   // B*M*C*G
    const double Nf  = 8.0 * 16.0 * 3.0 * 8320.0;    // B*M*C*Gf (Gf = 128*65)
    double crps_p = S1  / Np - (1.0 - eps) * S2p  / (15.0 * Np);
    double crps_f = S1f / Nf - (1.0 - eps) * S2fp / (15.0 * Nf);
    out[0] = (float)(crps_p + 0.1 * crps_f);
}

extern "C" void kernel_launch(void* const* d_in, const int* in_sizes, int n_in,
                              void* d_out, int out_size) {
    const float* target = (const float*)d_in[0];
    const float* output = (const float*)d_in[1];
    if (in_sizes[0] > in_sizes[1]) {  // defensive: identify by element count
        const float* tmp = target; target = output; output = tmp;
    }
    float* out = (float*)d_out;

    k_zero<<<1, 32>>>();
    // pointwise CRPS partials: 393216 sites (CG = 3*16384 = 49152)
    k_crps<<<1536, 256>>>(output, target, 49152, 393216, 0);
    // pruned low-pass DFT magnitudes for 384 member images + 24 target images
    k_fft<<<NIMG_OUT + NIMG_TGT, 256>>>(output, target);
    // frequency CRPS partials: 12288 active bins (CG = 3*512 = 1536)
    k_crps<<<48, 256>>>(nullptr, nullptr, 1536, 12288, 2);
    k_final<<<1, 1>>>(out);
}

// round 2
// speedup vs baseline: 1.0031x; 1.0031x over previous
#include <cuda_runtime.h>
#include <math.h>

// Problem constants
// target: (8, 3, 128, 128)       = 393216 floats
// output: (8, 16, 3, 128, 128)   = 6291456 floats
// out: scalar float
//
// crps(pred(B,M,C,G), tgt(B,C,G)) = S1/(B*M*C*G) - (1-eps)*S2p/((M-1)*B*M*C*G)
//   S1  = sum |p_m - t|, S2p = sum_{i<j} |p_i - p_j|, eps = 0.05/M
// Spectral term: rfft2 low-pass mask keeps bins (kh<32, kw<16); masked-out bins
// contribute exactly 0 to both sums but the means divide by Gf = 128*65 = 8320.

#define NIMG_OUT 384      // B*M*C
#define NIMG_TGT 24       // B*C
#define NBINS    512      // 32*16 active bins

__device__ double g_acc[4];                 // S1, S2p, S1f, S2fp
__device__ float  g_magM[NIMG_OUT * NBINS];
__device__ float  g_magT[NIMG_TGT * NBINS];

__global__ void k_zero() {
    if (threadIdx.x < 4) g_acc[threadIdx.x] = 0.0;
}

__device__ __forceinline__ void reduce_and_add(float s1, float s2, int accIdx) {
    #pragma unroll
    for (int o = 16; o > 0; o >>= 1) {
        s1 += __shfl_down_sync(0xffffffffu, s1, o);
        s2 += __shfl_down_sync(0xffffffffu, s2, o);
    }
    __shared__ float sh1[8], sh2[8];
    int lane = threadIdx.x & 31, wid = threadIdx.x >> 5;
    if (lane == 0) { sh1[wid] = s1; sh2[wid] = s2; }
    __syncthreads();
    if (wid == 0) {
        int nw = blockDim.x >> 5;
        s1 = (lane < nw) ? sh1[lane] : 0.f;
        s2 = (lane < nw) ? sh2[lane] : 0.f;
        #pragma unroll
        for (int o = 4; o > 0; o >>= 1) {
            s1 += __shfl_down_sync(0xffffffffu, s1, o);
            s2 += __shfl_down_sync(0xffffffffu, s2, o);
        }
        if (lane == 0) {
            atomicAdd(&g_acc[accIdx],     (double)s1);
            atomicAdd(&g_acc[accIdx + 1], (double)s2);
        }
    }
}

// Unified CRPS partial-sum kernel.
// pred layout: pred[b*16*CG + m*CG + r], tgt layout: tgt[b*CG + r], idx = b*CG + r.
// accIdx==2 selects the on-device magnitude scratch (frequency branch).
__global__ void k_crps(const float* __restrict__ pred, const float* __restrict__ tgt,
                       int CG, int total, int accIdx) {
    if (accIdx == 2) { pred = g_magM; tgt = g_magT; }
    int idx = blockIdx.x * blockDim.x + threadIdx.x;
    float s1 = 0.f, s2 = 0.f;
    if (idx < total) {
        int b = idx / CG;
        int r = idx - b * CG;
        float t = tgt[idx];
        const float* base = pred + (size_t)b * 16 * CG + r;
        float p[16];
        #pragma unroll
        for (int m = 0; m < 16; m++) p[m] = base[(size_t)m * CG];
        #pragma unroll
        for (int i = 0; i < 16; i++) {
            s1 += fabsf(p[i] - t);
            #pragma unroll
            for (int j = i + 1; j < 16; j++) s2 += fabsf(p[i] - p[j]);
        }
    }
    reduce_and_add(s1, s2, accIdx);
}

// Pruned 2D DFT: per image compute X[kh,kw] for kh<32, kw<16 and store |X|.
// Stage 1: Y[h][kw] = sum_w x[h][w] * exp(-2pi i kw w / 128)   (real input)
// Stage 2: Z[kh][kw] = sum_h Y[h][kw] * exp(-2pi i kh h / 128)
// Blocks 0..383 -> output images, 384..407 -> target images.
__global__ void k_fft(const float* __restrict__ outp, const float* __restrict__ tgt) {
    int img = blockIdx.x;
    const float* src;
    float* dst;
    if (img < NIMG_OUT) { src = outp + (size_t)img * 16384;              dst = g_magM + img * NBINS; }
    else                { src = tgt  + (size_t)(img - NIMG_OUT) * 16384; dst = g_magT + (img - NIMG_OUT) * NBINS; }

    int tid = threadIdx.x;
    __shared__ float  sx[32 * 129];     // 32-row chunk, padded (conflict-free column walk)
    __shared__ float2 sy[128 * 16];     // stage-1 output (complex)
    __shared__ float2 stw[128];         // twiddle LUT exp(-2pi i j/128)

    if (tid < 128) {
        float s, c;
        sincosf(-6.283185307179586f * (float)tid / 128.0f, &s, &c);
        stw[tid] = make_float2(c, s);
    }

    int warp = tid >> 5, lane = tid & 31;
    int hl  = lane;        // row within 32-row chunk
    int kw0 = warp * 2;    // each warp handles 2 kw bins across all 32 rows

    #pragma unroll
    for (int chunk = 0; chunk < 4; chunk++) {
        __syncthreads();   // stw ready (iter 0) / sx consumed (iters 1+)
        for (int i = tid; i < 4096; i += 256)
            sx[(i >> 7) * 129 + (i & 127)] = src[chunk * 4096 + i];
        __syncthreads();

        int h = chunk * 32 + hl;
        float ar = 0.f, ai = 0.f, br = 0.f, bi = 0.f;
        #pragma unroll 8
        for (int w = 0; w < 128; w++) {
            float  x  = sx[hl * 129 + w];
            float2 t0 = stw[(kw0 * w) & 127];          // warp-uniform -> LDS broadcast
            float2 t1 = stw[((kw0 + 1) * w) & 127];
            ar = fmaf(x, t0.x, ar); ai = fmaf(x, t0.y, ai);
            br = fmaf(x, t1.x, br); bi = fmaf(x, t1.y, bi);
        }
        sy[h * 16 + kw0]     = make_float2(ar, ai);
        sy[h * 16 + kw0 + 1] = make_float2(br, bi);
    }
    __syncthreads();

    // Stage 2: thread -> (kw = tid&15, kh in {tid>>4, tid>>4 + 16}); shares Y loads.
    int kw  = tid & 15;
    int kh0 = tid >> 4;
    int kh1 = kh0 + 16;
    float z0r = 0.f, z0i = 0.f, z1r = 0.f, z1i = 0.f;
    #pragma unroll 4
    for (int h = 0; h < 128; h++) {
        float2 y  = sy[h * 16 + kw];
        float2 t0 = stw[(kh0 * h) & 127];
        float2 t1 = stw[(kh1 * h) & 127];
        z0r = fmaf(y.x, t0.x, fmaf(-y.y, t0.y, z0r));
        z0i = fmaf(y.x, t0.y, fmaf( y.y, t0.x, z0i));
        z1r = fmaf(y.x, t1.x, fmaf(-y.y, t1.y, z1r));
        z1i = fmaf(y.x, t1.y, fmaf( y.y, t1.x, z1i));
    }
    dst[kh0 * 16 + kw] = sqrtf(z0r * z0r + z0i * z0i);
    dst[kh1 * 16 + kw] = sqrtf(z1r * z1r + z1i * z1i);
}

__global__ void k_final(float* out) {
    double S1 = g_acc[0], S2p = g_acc[1], S1f = g_acc[2], S2fp = g_acc[3];
    const double eps = 0.05 / 16.0;
    const double Np  = 8.0 * 16.0 * 3.0 * 16384.0;   // B*M*C*G
    const double Nf  = 8.0 * 16.0 * 3.0 * 8320.0;    // B*M*C*Gf (Gf = 128*65)
    double crps_p = S1  / Np - (1.0 - eps) * S2p  / (15.0 * Np);
    double crps_f = S1f / Nf - (1.0 - eps) * S2fp / (15.0 * Nf);
    out[0] = (float)(crps_p + 0.1 * crps_f);
}

extern "C" void kernel_launch(void* const* d_in, const int* in_sizes, int n_in,
                              void* d_out, int out_size) {
    const float* target = (const float*)d_in[0];
    const float* output = (const float*)d_in[1];
    if (in_sizes[0] > in_sizes[1]) {  // defensive: identify by element count
        const float* tmp = target; target = output; output = tmp;
    }
    float* out = (float*)d_out;

    k_zero<<<1, 32>>>();
    // pointwise CRPS partials: 393216 sites (CG = 3*16384 = 49152)
    k_crps<<<1536, 256>>>(output, target, 49152, 393216, 0);
    // pruned low-pass DFT magnitudes for 384 member images + 24 target images
    k_fft<<<NIMG_OUT + NIMG_TGT, 256>>>(output, target);
    // frequency CRPS partials: 12288 active bins (CG = 3*512 = 1536)
    k_crps<<<48, 256>>>(nullptr, nullptr, 1536, 12288, 2);
    k_final<<<1, 1>>>(out);
}

// round 3
// speedup vs baseline: 1.3174x; 1.3133x over previous
#include <cuda_runtime.h>
#include <math.h>

// target: (8, 3, 128, 128) = 393216 f32 ; output: (8, 16, 3, 128, 128) = 6291456 f32
// loss = crps_p + 0.1 * crps_f
// crps(pred,tgt) = S1/N - (1-eps)*S2 / ((M-1)*N),  S2 = sum over ordered pairs i<j (x2 handled in finalize)
// Spectral: rfft2 low-pass keeps bins kh<32, kw<16; masked bins contribute 0 to sums,
// means divide by Gf = 128*65 = 8320.

#define NIMG_OUT 384
#define NIMG_TGT 24
#define NBINS    512          // 32*16 active bins per image

typedef unsigned long long u64;

__device__ double g_acc[4];                 // S1, S2p, S1f, S2fp
__device__ float  g_magM[NIMG_OUT * NBINS];
__device__ float  g_magT[NIMG_TGT * NBINS];

// ---------- packed f32x2 helpers ----------
__device__ __forceinline__ u64 pack2(float lo, float hi) {
    u64 r; asm("mov.b64 %0, {%1, %2};" : "=l"(r) : "f"(lo), "f"(hi)); return r;
}
__device__ __forceinline__ void unpack2(u64 v, float& lo, float& hi) {
    asm("mov.b64 {%0, %1}, %2;" : "=f"(lo), "=f"(hi) : "l"(v));
}
__device__ __forceinline__ u64 fma2(u64 a, u64 b, u64 c) {
    u64 d; asm("fma.rn.f32x2 %0, %1, %2, %3;" : "=l"(d) : "l"(a), "l"(b), "l"(c)); return d;
}
__device__ __forceinline__ void lds_v2u64(unsigned addr, u64& a, u64& b) {
    asm volatile("ld.shared.v2.u64 {%0, %1}, [%2];" : "=l"(a), "=l"(b) : "r"(addr));
}
__device__ __forceinline__ unsigned smem_u32(const void* p) {
    unsigned r;
    asm("{ .reg .u64 t; cvta.to.shared.u64 t, %1; cvt.u32.u64 %0, t; }" : "=r"(r) : "l"(p));
    return r;
}

// ---------- shared-memory layout for k_fft (dynamic, 100352 bytes) ----------
// floats:  sx[2][32*132]          : 8448 f   (two 32-row chunks, stride 132 -> LDS.128-friendly, conflict-free)
// u64:     sy[128*17]             : 2176 u64 (stage-1 complex output, stride 17 kills the h-major conflict)
// f2:      lut1[128*16]           : exp(-2pi i (kw*w mod 128)/128), w-major -> adjacent kw pairs, 16B loads
// f4:      lut2[128*16]           : (c,s) for kh and kh+16 packed per entry -> one 16B broadcast per h
#define OFF_SY_F   8448            // in floats
#define OFF_LUT1_F (8448 + 4352)   // sy = 2176 u64 = 4352 floats
#define OFF_LUT2_F (OFF_LUT1_F + 4096)
#define SMEM_FFT_BYTES ((OFF_LUT2_F + 8192) * 4)   // 100352

__global__ void k_fft(const float* __restrict__ outp, const float* __restrict__ tgt) {
    extern __shared__ float smemf[];
    const int img = blockIdx.x;
    const int tid = threadIdx.x;

    if (img == 0 && tid < 4) g_acc[tid] = 0.0;   // runs before any CRPS kernel in-stream

    const float* src;
    float* dst;
    if (img < NIMG_OUT) { src = outp + (size_t)img * 16384;              dst = g_magM + img * NBINS; }
    else                { src = tgt  + (size_t)(img - NIMG_OUT) * 16384; dst = g_magT + (img - NIMG_OUT) * NBINS; }

    const unsigned sb       = smem_u32(smemf);
    const unsigned lut1_u   = sb + OFF_LUT1_F * 4;
    const unsigned lut2_u   = sb + OFF_LUT2_F * 4;
    u64*   syu   = (u64*)(smemf + OFF_SY_F);
    float2* lut1 = (float2*)(smemf + OFF_LUT1_F);
    float4* lut2 = (float4*)(smemf + OFF_LUT2_F);

    // Build twiddle LUTs (2048 entries each)
    const float C = -6.283185307179586f / 128.0f;
    #pragma unroll
    for (int i = 0; i < 8; i++) {
        int idx = tid + i * 256;
        int w = idx >> 4, k = idx & 15;
        float s0, c0, s1, c1;
        sincosf(C * (float)((w * k) & 127), &s0, &c0);
        lut1[idx] = make_float2(c0, s0);
        // lut2: idx -> (h = idx>>4, kh0 = idx&15); pack kh0 and kh0+16
        sincosf(C * (float)(((k + 16) * w) & 127), &s1, &c1);
        lut2[idx] = make_float4(c0, s0, c1, s1);   // (kh0*h) reuses same product k*w
    }

    const int warp = tid >> 5, lane = tid & 31;
    const int wg = warp >> 2;             // 0/1 -> which in-flight chunk
    const int kwbase = (warp & 3) * 4;    // 4 kw bins per warp

    // ---------------- stage 1: per-row 128 -> 16 bins ----------------
    #pragma unroll
    for (int round = 0; round < 2; round++) {
        __syncthreads();
        // load two 32-row chunks (2048 float4) cooperatively
        const float4* src4 = (const float4*)src;
        #pragma unroll
        for (int i = 0; i < 8; i++) {
            int e = tid + i * 256;            // 0..2047
            int half = e >> 10, j = e & 1023; // chunk-half, element
            int row = j >> 5, col4 = j & 31;
            *(float4*)(smemf + half * 4224 + row * 132 + col4 * 4) =
                src4[(round * 2 + half) * 1024 + j];
        }
        __syncthreads();

        const float* myrow = smemf + wg * 4224 + lane * 132;
        u64 acc0 = 0, acc1 = 0, acc2 = 0, acc3 = 0;
        const unsigned tbase = lut1_u + kwbase * 8;
        #pragma unroll 4
        for (int w4 = 0; w4 < 32; w4++) {
            float4 xv = *(const float4*)(myrow + w4 * 4);
            #pragma unroll
            for (int s = 0; s < 4; s++) {
                int w = w4 * 4 + s;
                float x = (s == 0) ? xv.x : (s == 1) ? xv.y : (s == 2) ? xv.z : xv.w;
                u64 xx = pack2(x, x);
                u64 tA, tB, tC, tD;
                lds_v2u64(tbase + w * 128, tA, tB);        // bins kwbase, kwbase+1
                lds_v2u64(tbase + w * 128 + 16, tC, tD);   // bins kwbase+2, kwbase+3
                acc0 = fma2(xx, tA, acc0);
                acc1 = fma2(xx, tB, acc1);
                acc2 = fma2(xx, tC, acc2);
                acc3 = fma2(xx, tD, acc3);
            }
        }
        int h = (round * 2 + wg) * 32 + lane;
        u64* d = syu + h * 17 + kwbase;
        d[0] = acc0; d[1] = acc1; d[2] = acc2; d[3] = acc3;
    }
    __syncthreads();

    // ---------------- stage 2: per-column 128 -> 32 bins ----------------
    const int kw  = tid & 15;
    const int kh0 = tid >> 4;           // 0..15 ; also handles kh0+16
    u64 U0 = 0, V0 = 0, U1 = 0, V1 = 0;
    #pragma unroll 4
    for (int h = 0; h < 128; h++) {
        u64 y = syu[h * 17 + kw];
        float yr, yi; unpack2(y, yr, yi);
        u64 yr2 = pack2(yr, yr), yi2 = pack2(yi, yi);
        u64 t0, t1;
        lds_v2u64(lut2_u + (h * 16 + kh0) * 16, t0, t1);   // t0 = (c,s) for kh0 ; t1 for kh0+16
        U0 = fma2(yr2, t0, U0);
        V0 = fma2(yi2, t0, V0);
        U1 = fma2(yr2, t1, U1);
        V1 = fma2(yi2, t1, V1);
    }
    float u0l, u0h, v0l, v0h, u1l, u1h, v1l, v1h;
    unpack2(U0, u0l, u0h); unpack2(V0, v0l, v0h);
    unpack2(U1, u1l, u1h); unpack2(V1, v1l, v1h);
    float zr0 = u0l - v0h, zi0 = u0h + v0l;
    float zr1 = u1l - v1h, zi1 = u1h + v1l;
    dst[kh0 * 16 + kw]        = sqrtf(zr0 * zr0 + zi0 * zi0);
    dst[(kh0 + 16) * 16 + kw] = sqrtf(zr1 * zr1 + zi1 * zi1);
}

// ---------------- CRPS reduction ----------------
__device__ __forceinline__ void reduce_and_add(float s1, float s2, int accIdx) {
    #pragma unroll
    for (int o = 16; o > 0; o >>= 1) {
        s1 += __shfl_down_sync(0xffffffffu, s1, o);
        s2 += __shfl_down_sync(0xffffffffu, s2, o);
    }
    __shared__ float sh1[8], sh2[8];
    int lane = threadIdx.x & 31, wid = threadIdx.x >> 5;
    if (lane == 0) { sh1[wid] = s1; sh2[wid] = s2; }
    __syncthreads();
    if (wid == 0) {
        s1 = (lane < 8) ? sh1[lane] : 0.f;
        s2 = (lane < 8) ? sh2[lane] : 0.f;
        #pragma unroll
        for (int o = 4; o > 0; o >>= 1) {
            s1 += __shfl_down_sync(0xffffffffu, s1, o);
            s2 += __shfl_down_sync(0xffffffffu, s2, o);
        }
        if (lane == 0) {
            atomicAdd(&g_acc[accIdx],     (double)s1);
            atomicAdd(&g_acc[accIdx + 1], (double)s2);
        }
    }
}

// Merged CRPS: blocks [0,384) pointwise (float4-vectorized), blocks [384,432) frequency.
__global__ void k_crps2(const float* __restrict__ outp, const float* __restrict__ tgt) {
    float s1 = 0.f, s2 = 0.f;
    int accIdx;
    if (blockIdx.x < 384) {
        accIdx = 0;
        int t4 = blockIdx.x * 256 + threadIdx.x;   // 0..98303, 4 pixels each
        int b  = t4 / 12288;                       // CG/4 = 12288 float4 per (b)
        int r4 = t4 - b * 12288;
        float4 tv = ((const float4*)tgt)[b * 12288 + r4];
        const float4* base = (const float4*)outp + (size_t)b * 196608 + r4;   // 16*CG/4 per b
        float4 p[16];
        #pragma unroll
        for (int m = 0; m < 16; m++) p[m] = base[m * 12288];
        #pragma unroll
        for (int i = 0; i < 16; i++) {
            s1 += fabsf(p[i].x - tv.x) + fabsf(p[i].y - tv.y)
                + fabsf(p[i].z - tv.z) + fabsf(p[i].w - tv.w);
            #pragma unroll
            for (int j = i + 1; j < 16; j++) {
                s2 += fabsf(p[i].x - p[j].x) + fabsf(p[i].y - p[j].y)
                    + fabsf(p[i].z - p[j].z) + fabsf(p[i].w - p[j].w);
            }
        }
    } else {
        accIdx = 2;
        int idx = (blockIdx.x - 384) * 256 + threadIdx.x;   // 0..12287
        int b = idx / 1536;
        int r = idx - b * 1536;
        float t = g_magT[idx];
        const float* base = g_magM + b * 16 * 1536 + r;
        float p[16];
        #pragma unroll
        for (int m = 0; m < 16; m++) p[m] = base[m * 1536];
        #pragma unroll
        for (int i = 0; i < 16; i++) {
            s1 += fabsf(p[i] - t);
            #pragma unroll
            for (int j = i + 1; j < 16; j++) s2 += fabsf(p[i] - p[j]);
        }
    }
    reduce_and_add(s1, s2, accIdx);
}

__global__ void k_final(float* out) {
    double S1 = g_acc[0], S2p = g_acc[1], S1f = g_acc[2], S2fp = g_acc[3];
    const double eps = 0.05 / 16.0;
    const double Np  = 8.0 * 16.0 * 3.0 * 16384.0;
    const double Nf  = 8.0 * 16.0 * 3.0 * 8320.0;
    double crps_p = S1  / Np - (1.0 - eps) * S2p  / (15.0 * Np);
    double crps_f = S1f / Nf - (1.0 - eps) * S2fp / (15.0 * Nf);
    out[0] = (float)(crps_p + 0.1 * crps_f);
}

extern "C" void kernel_launch(void* const* d_in, const int* in_sizes, int n_in,
                              void* d_out, int out_size) {
    const float* target = (const float*)d_in[0];
    const float* output = (const float*)d_in[1];
    if (in_sizes[0] > in_sizes[1]) {
        const float* tmp = target; target = output; output = tmp;
    }
    float* out = (float*)d_out;

    static int smem_set = 0;
    if (!smem_set) {
        cudaFuncSetAttribute(k_fft, cudaFuncAttributeMaxDynamicSharedMemorySize, SMEM_FFT_BYTES);
        smem_set = 1;
    }

    k_fft<<<NIMG_OUT + NIMG_TGT, 256, SMEM_FFT_BYTES>>>(output, target);
    k_crps2<<<432, 256>>>(output, target);
    k_final<<<1, 1>>>(out);
}

// round 5
// speedup vs baseline: 1.4491x; 1.1000x over previous
#include <cuda_runtime.h>
#include <math.h>

// target: (8, 3, 128, 128) = 393216 f32 ; output: (8, 16, 3, 128, 128) = 6291456 f32
// loss = crps_p + 0.1*crps_f ; spectral branch keeps rfft2 bins kh<32, kw<16,
// masked bins contribute 0 but means divide by Gf = 128*65 = 8320.

typedef unsigned long long u64;

#define NIMG_OUT 384
#define NIMG_TGT 24
#define NIMG     408
#define NBINS    512

__device__ double   g_acc[4];     // S1, S2p, S1f, S2fp   (zero-init; re-zeroed by finalize)
__device__ unsigned g_done;       // completion counter   (zero-init; re-zeroed by finalize)
__device__ float    g_magM[NIMG_OUT * NBINS];
__device__ float    g_magT[NIMG_TGT * NBINS];

// ---------------- compile-time twiddles (device-legal constexpr, no host table) ----------------
__host__ __device__ constexpr double ccos(double x) {
    double t = 1.0, s = 1.0, x2 = x * x;
    for (int n = 1; n < 16; n++) { t *= -x2 / ((2 * n - 1) * (2 * n)); s += t; }
    return s;
}
__host__ __device__ constexpr double csin(double x) {
    double t = x, s = x, x2 = x * x;
    for (int n = 1; n < 16; n++) { t *= -x2 / ((2 * n) * (2 * n + 1)); s += t; }
    return s;
}
__host__ __device__ constexpr double ang(int j) {
    int m = j & 127;
    int jj = (m <= 64) ? m : m - 128;            // range-reduce to [-pi, pi]
    return -2.0 * 3.14159265358979323846 * (double)jj / 128.0;
}
template<int J> __device__ __forceinline__ float TWC() {
    constexpr float v = (float)ccos(ang(J)); return v;
}
template<int J> __device__ __forceinline__ float TWS() {
    constexpr float v = (float)csin(ang(J)); return v;
}

// ---------------- stage-1: fully unrolled FFMA-imm DFT (4 bins per warp) ----------------
template<int KWB, int W>
__device__ __forceinline__ void s1step(float x, float* a) {
    a[0] = fmaf(x, TWC<(KWB + 0) * W>(), a[0]);  a[1] = fmaf(x, TWS<(KWB + 0) * W>(), a[1]);
    a[2] = fmaf(x, TWC<(KWB + 1) * W>(), a[2]);  a[3] = fmaf(x, TWS<(KWB + 1) * W>(), a[3]);
    a[4] = fmaf(x, TWC<(KWB + 2) * W>(), a[4]);  a[5] = fmaf(x, TWS<(KWB + 2) * W>(), a[5]);
    a[6] = fmaf(x, TWC<(KWB + 3) * W>(), a[6]);  a[7] = fmaf(x, TWS<(KWB + 3) * W>(), a[7]);
}
template<int KWB, int W4> struct S1 {
    static __device__ __forceinline__ void run(const float* row, float* a) {
        float4 xv = *(const float4*)(row + W4 * 4);
        s1step<KWB, 4 * W4 + 0>(xv.x, a);
        s1step<KWB, 4 * W4 + 1>(xv.y, a);
        s1step<KWB, 4 * W4 + 2>(xv.z, a);
        s1step<KWB, 4 * W4 + 3>(xv.w, a);
        S1<KWB, W4 + 1>::run(row, a);
    }
};
template<int KWB> struct S1<KWB, 32> {
    static __device__ __forceinline__ void run(const float*, float*) {}
};

// ---------------- packed f32x2 helpers ----------------
__device__ __forceinline__ u64 pack2(float lo, float hi) {
    u64 r; asm("mov.b64 %0, {%1, %2};" : "=l"(r) : "f"(lo), "f"(hi)); return r;
}
__device__ __forceinline__ void unpack2(u64 v, float& lo, float& hi) {
    asm("mov.b64 {%0, %1}, %2;" : "=f"(lo), "=f"(hi) : "l"(v));
}
__device__ __forceinline__ u64 fma2(u64 a, u64 b, u64 c) {
    u64 d; asm("fma.rn.f32x2 %0, %1, %2, %3;" : "=l"(d) : "l"(a), "l"(b), "l"(c)); return d;
}

// ---------------- smem layout (52224 bytes dynamic) ----------------
// sx : float[2][32][132]   8448 f  (two 32-row chunks; stride 132 -> conflict-free LDS.128)
// sy : u64[128*17]         4352 f  (stage-1 complex output; stride 17 -> conflict-free)
// lut: float2[128]          256 f  (stage-2 base twiddles)
#define SX_STRIDE 132
#define OFF_SY_F  (2 * 32 * SX_STRIDE)       // 8448
#define OFF_LUT_F (OFF_SY_F + 4352)          // 12800
#define SMEM_BYTES ((OFF_LUT_F + 256) * 4)   // 52224

__device__ __forceinline__ void reduce_and_add(float s1, float s2, int accIdx) {
    #pragma unroll
    for (int o = 16; o > 0; o >>= 1) {
        s1 += __shfl_down_sync(0xffffffffu, s1, o);
        s2 += __shfl_down_sync(0xffffffffu, s2, o);
    }
    __shared__ float sh1[8], sh2[8];
    int lane = threadIdx.x & 31, wid = threadIdx.x >> 5;
    if (lane == 0) { sh1[wid] = s1; sh2[wid] = s2; }
    __syncthreads();
    if (wid == 0) {
        s1 = (lane < 8) ? sh1[lane] : 0.f;
        s2 = (lane < 8) ? sh2[lane] : 0.f;
        #pragma unroll
        for (int o = 4; o > 0; o >>= 1) {
            s1 += __shfl_down_sync(0xffffffffu, s1, o);
            s2 += __shfl_down_sync(0xffffffffu, s2, o);
        }
        if (lane == 0) {
            atomicAdd(&g_acc[accIdx],     (double)s1);
            atomicAdd(&g_acc[accIdx + 1], (double)s2);
        }
    }
}

// Heterogeneous kernel: blocks [0,408) = pruned DFT per image; blocks [408,792) = pointwise CRPS.
__global__ void k_main(const float* __restrict__ outp, const float* __restrict__ tgt) {
    const int tid = threadIdx.x;

    if (blockIdx.x >= NIMG) {
        // ---------------- pointwise CRPS (float4-vectorized) ----------------
        int t4 = (blockIdx.x - NIMG) * 256 + tid;   // 0..98303
        int b  = t4 / 12288;                        // CG/4 = 12288 float4 per batch
        int r4 = t4 - b * 12288;
        float4 tv = ((const float4*)tgt)[b * 12288 + r4];
        const float4* base = (const float4*)outp + (size_t)b * 196608 + r4;
        float4 p[16];
        #pragma unroll
        for (int m = 0; m < 16; m++) p[m] = base[m * 12288];
        float s1 = 0.f, s2 = 0.f;
        #pragma unroll
        for (int i = 0; i < 16; i++) {
            s1 += fabsf(p[i].x - tv.x) + fabsf(p[i].y - tv.y)
                + fabsf(p[i].z - tv.z) + fabsf(p[i].w - tv.w);
            #pragma unroll
            for (int j = i + 1; j < 16; j++) {
                s2 += fabsf(p[i].x - p[j].x) + fabsf(p[i].y - p[j].y)
                    + fabsf(p[i].z - p[j].z) + fabsf(p[i].w - p[j].w);
            }
        }
        reduce_and_add(s1, s2, 0);
        return;
    }

    // ---------------- pruned low-pass 2D DFT ----------------
    extern __shared__ float smemf[];
    u64*    syu  = (u64*)(smemf + OFF_SY_F);
    float2* lut  = (float2*)(smemf + OFF_LUT_F);

    const int img = blockIdx.x;
    const float* src;
    float* dst;
    if (img < NIMG_OUT) { src = outp + (size_t)img * 16384;              dst = g_magM + img * NBINS; }
    else                { src = tgt  + (size_t)(img - NIMG_OUT) * 16384; dst = g_magT + (img - NIMG_OUT) * NBINS; }

    if (tid < 128) {
        float s, c;
        sincosf(-6.283185307179586f * (float)tid / 128.0f, &s, &c);
        lut[tid] = make_float2(c, s);
    }

    const int warp = tid >> 5, lane = tid & 31;
    const int wg   = warp >> 2;            // chunk within round
    const int kwb  = (warp & 3) * 4;       // 4 kw bins per warp

    #pragma unroll
    for (int round = 0; round < 2; round++) {
        __syncthreads();
        const float4* src4 = (const float4*)src;
        #pragma unroll
        for (int i = 0; i < 8; i++) {
            int e = tid + i * 256;             // 0..2047 float4s (64 rows)
            int half = e >> 10, j = e & 1023;
            int row = j >> 5, col4 = j & 31;
            *(float4*)(smemf + half * 32 * SX_STRIDE + row * SX_STRIDE + col4 * 4) =
                src4[(round * 2 + half) * 1024 + j];
        }
        __syncthreads();

        const float* myrow = smemf + wg * 32 * SX_STRIDE + lane * SX_STRIDE;
        float a[8];
        #pragma unroll
        for (int i = 0; i < 8; i++) a[i] = 0.f;
        if      (kwb == 0)  S1<0,  0>::run(myrow, a);
        else if (kwb == 4)  S1<4,  0>::run(myrow, a);
        else if (kwb == 8)  S1<8,  0>::run(myrow, a);
        else                S1<12, 0>::run(myrow, a);

        int h = round * 64 + wg * 32 + lane;
        u64* d = syu + h * 17 + kwb;
        d[0] = pack2(a[0], a[1]); d[1] = pack2(a[2], a[3]);
        d[2] = pack2(a[4], a[5]); d[3] = pack2(a[6], a[7]);
    }
    __syncthreads();

    // stage 2: thread -> (kw = tid&15, kh in {tid>>4, tid>>4+16})
    const int kw  = tid & 15;
    const int kh0 = tid >> 4;
    const int kh1 = kh0 + 16;
    u64 U0 = 0, V0 = 0, U1 = 0, V1 = 0;
    #pragma unroll 8
    for (int h = 0; h < 128; h++) {
        u64 y = syu[h * 17 + kw];
        float yr, yi; unpack2(y, yr, yi);
        u64 yr2 = pack2(yr, yr), yi2 = pack2(yi, yi);
        u64 t0 = *(const u64*)&lut[(kh0 * h) & 127];
        u64 t1 = *(const u64*)&lut[(kh1 * h) & 127];
        U0 = fma2(yr2, t0, U0);
        V0 = fma2(yi2, t0, V0);
        U1 = fma2(yr2, t1, U1);
        V1 = fma2(yi2, t1, V1);
    }
    float u0l, u0h, v0l, v0h, u1l, u1h, v1l, v1h;
    unpack2(U0, u0l, u0h); unpack2(V0, v0l, v0h);
    unpack2(U1, u1l, u1h); unpack2(V1, v1l, v1h);
    float zr0 = u0l - v0h, zi0 = u0h + v0l;
    float zr1 = u1l - v1h, zi1 = u1h + v1l;
    dst[kh0 * 16 + kw] = sqrtf(zr0 * zr0 + zi0 * zi0);
    dst[kh1 * 16 + kw] = sqrtf(zr1 * zr1 + zi1 * zi1);
}

// Frequency CRPS + last-block finalize (48 blocks x 256 = 12288 active bins).
__global__ void k_freqfinal(float* out) {
    int tid = threadIdx.x;
    int idx = blockIdx.x * 256 + tid;
    int b = idx / 1536;
    int r = idx - b * 1536;
    float t = g_magT[idx];
    const float* base = g_magM + b * 16 * 1536 + r;
    float p[16];
    #pragma unroll
    for (int m = 0; m < 16; m++) p[m] = base[m * 1536];
    float s1 = 0.f, s2 = 0.f;
    #pragma unroll
    for (int i = 0; i < 16; i++) {
        s1 += fabsf(p[i] - t);
        #pragma unroll
        for (int j = i + 1; j < 16; j++) s2 += fabsf(p[i] - p[j]);
    }
    reduce_and_add(s1, s2, 2);

    __shared__ bool isLast;
    if (tid == 0) {
        __threadfence();
        unsigned prev = atomicAdd(&g_done, 1u);
        isLast = (prev == 47u);
    }
    __syncthreads();
    if (isLast && tid == 0) {
        __threadfence();
        double S1  = g_acc[0], S2p  = g_acc[1];
        double S1f = g_acc[2], S2fp = g_acc[3];
        const double eps = 0.05 / 16.0;
        const double Np  = 8.0 * 16.0 * 3.0 * 16384.0;
        const double Nf  = 8.0 * 16.0 * 3.0 * 8320.0;
        double crps_p = S1  / Np - (1.0 - eps) * S2p  / (15.0 * Np);
        double crps_f = S1f / Nf - (1.0 - eps) * S2fp / (15.0 * Nf);
        out[0] = (float)(crps_p + 0.1 * crps_f);
        // reset for the next graph replay
        g_acc[0] = 0.0; g_acc[1] = 0.0; g_acc[2] = 0.0; g_acc[3] = 0.0;
        __threadfence();
        g_done = 0u;
    }
}

extern "C" void kernel_launch(void* const* d_in, const int* in_sizes, int n_in,
                              void* d_out, int out_size) {
    const float* target = (const float*)d_in[0];
    const float* output = (const float*)d_in[1];
    if (in_sizes[0] > in_sizes[1]) {
        const float* tmp = target; target = output; output = tmp;
    }
    float* out = (float*)d_out;

    static int smem_set = 0;
    if (!smem_set) {
        cudaFuncSetAttribute(k_main, cudaFuncAttributeMaxDynamicSharedMemorySize, SMEM_BYTES);
        smem_set = 1;
    }

    // blocks [0,408): per-image pruned DFT ; blocks [408,792): pointwise CRPS (overlapped)
    k_main<<<NIMG + 384, 256, SMEM_BYTES>>>(output, target);
    // frequency CRPS + finalize (+accumulator reset for next replay)
    k_freqfinal<<<48, 256>>>(out);
}

// round 6
// speedup vs baseline: 1.8960x; 1.3084x over previous
#include <cuda_runtime.h>
#include <math.h>

// target: (8, 3, 128, 128) = 393216 f32 ; output: (8, 16, 3, 128, 128) = 6291456 f32
// loss = crps_p + 0.1*crps_f ; spectral branch keeps rfft2 bins kh<32, kw<16,
// masked bins contribute 0 but means divide by Gf = 128*65 = 8320.

typedef unsigned long long u64;

#define NIMG_OUT 384
#define NIMG_TGT 24
#define NIMG     408
#define NBINS    512
#define NCRPS_BLK 768     // 393216 pixels / 2 per thread / 256 threads

__device__ double   g_acc[4];     // S1, S2p, S1f, S2fp (zero-init; re-zeroed by finalize)
__device__ unsigned g_done;
// magnitudes stored member-contiguous: g_magM[(bc*512 + bin)*16 + m], bc = b*3+c
__device__ float    g_magM[NIMG_TGT * NBINS * 16];
__device__ float    g_magT[NIMG_TGT * NBINS];

// ---------------- compile-time twiddles ----------------
__host__ __device__ constexpr double ccos(double x) {
    double t = 1.0, s = 1.0, x2 = x * x;
    for (int n = 1; n < 16; n++) { t *= -x2 / ((2 * n - 1) * (2 * n)); s += t; }
    return s;
}
__host__ __device__ constexpr double csin(double x) {
    double t = x, s = x, x2 = x * x;
    for (int n = 1; n < 16; n++) { t *= -x2 / ((2 * n) * (2 * n + 1)); s += t; }
    return s;
}
__host__ __device__ constexpr double ang(int j) {
    int m = j & 127;
    int jj = (m <= 64) ? m : m - 128;
    return -2.0 * 3.14159265358979323846 * (double)jj / 128.0;
}
template<int J> __device__ __forceinline__ float TWC() {
    constexpr float v = (float)ccos(ang(J)); return v;
}
template<int J> __device__ __forceinline__ float TWS() {
    constexpr float v = (float)csin(ang(J)); return v;
}

// stage-1: two bins (K0,K1 same parity) over a 64-float half-row, FFMA-imm only
template<int K0, int K1, int W>
__device__ __forceinline__ void s1pair(float x, float* a) {
    a[0] = fmaf(x, TWC<K0 * W>(), a[0]);  a[1] = fmaf(x, TWS<K0 * W>(), a[1]);
    a[2] = fmaf(x, TWC<K1 * W>(), a[2]);  a[3] = fmaf(x, TWS<K1 * W>(), a[3]);
}
template<int K0, int K1, int W4> struct S1R {
    static __device__ __forceinline__ void run(const float* p, float* a) {
        float4 v = *(const float4*)(p + W4 * 4);
        s1pair<K0, K1, 4 * W4 + 0>(v.x, a);
        s1pair<K0, K1, 4 * W4 + 1>(v.y, a);
        s1pair<K0, K1, 4 * W4 + 2>(v.z, a);
        s1pair<K0, K1, 4 * W4 + 3>(v.w, a);
        S1R<K0, K1, W4 + 1>::run(p, a);
    }
};
template<int K0, int K1> struct S1R<K0, K1, 16> {
    static __device__ __forceinline__ void run(const float*, float*) {}
};

// ---------------- packed f32x2 helpers ----------------
__device__ __forceinline__ u64 pack2(float lo, float hi) {
    u64 r; asm("mov.b64 %0, {%1, %2};" : "=l"(r) : "f"(lo), "f"(hi)); return r;
}
__device__ __forceinline__ void unpack2(u64 v, float& lo, float& hi) {
    asm("mov.b64 {%0, %1}, %2;" : "=f"(lo), "=f"(hi) : "l"(v));
}
__device__ __forceinline__ u64 fma2(u64 a, u64 b, u64 c) {
    u64 d; asm("fma.rn.f32x2 %0, %1, %2, %3;" : "=l"(d) : "l"(a), "l"(b), "l"(c)); return d;
}

// ---------------- smem layout (52224 B dynamic) ----------------
// sx : float[2][32][132]  (per 32-row chunk: s at cols [0,64), d at [64,128), pad 4)
// sy : u64[128*17]        stage-1 complex output, stride 17 -> conflict-free
// lut: float2[128]        stage-2 base twiddles
#define SX_STRIDE 132
#define OFF_SY_F  (2 * 32 * SX_STRIDE)       // 8448
#define OFF_LUT_F (OFF_SY_F + 4352)          // 12800
#define SMEM_BYTES ((OFF_LUT_F + 256) * 4)   // 52224

__device__ __forceinline__ void reduce_and_add(float s1, float s2, int accIdx) {
    #pragma unroll
    for (int o = 16; o > 0; o >>= 1) {
        s1 += __shfl_down_sync(0xffffffffu, s1, o);
        s2 += __shfl_down_sync(0xffffffffu, s2, o);
    }
    __shared__ float sh1[8], sh2[8];
    int lane = threadIdx.x & 31, wid = threadIdx.x >> 5;
    if (lane == 0) { sh1[wid] = s1; sh2[wid] = s2; }
    __syncthreads();
    if (wid == 0) {
        s1 = (lane < 8) ? sh1[lane] : 0.f;
        s2 = (lane < 8) ? sh2[lane] : 0.f;
        #pragma unroll
        for (int o = 4; o > 0; o >>= 1) {
            s1 += __shfl_down_sync(0xffffffffu, s1, o);
            s2 += __shfl_down_sync(0xffffffffu, s2, o);
        }
        if (lane == 0) {
            atomicAdd(&g_acc[accIdx],     (double)s1);
            atomicAdd(&g_acc[accIdx + 1], (double)s2);
        }
    }
}

// blocks [0,408): pruned DFT per image ; blocks [408,408+768): pointwise CRPS (float2)
__global__ void __launch_bounds__(256, 4)
k_main(const float* __restrict__ outp, const float* __restrict__ tgt) {
    const int tid = threadIdx.x;

    if (blockIdx.x >= NIMG) {
        int t2 = (blockIdx.x - NIMG) * 256 + tid;   // 0..196607
        int b  = t2 / 24576;                        // CG/2 = 24576 float2 per batch
        int r2 = t2 - b * 24576;
        float2 tv = ((const float2*)tgt)[b * 24576 + r2];
        const float2* base = (const float2*)outp + (size_t)b * 393216 + r2;
        float2 p[16];
        #pragma unroll
        for (int m = 0; m < 16; m++) p[m] = base[m * 24576];
        float s1 = 0.f, s2 = 0.f;
        #pragma unroll
        for (int i = 0; i < 16; i++) {
            s1 += fabsf(p[i].x - tv.x) + fabsf(p[i].y - tv.y);
            #pragma unroll
            for (int j = i + 1; j < 16; j++)
                s2 += fabsf(p[i].x - p[j].x) + fabsf(p[i].y - p[j].y);
        }
        reduce_and_add(s1, s2, 0);
        return;
    }

    // ---------------- pruned low-pass 2D DFT ----------------
    extern __shared__ float smemf[];
    u64*    syu = (u64*)(smemf + OFF_SY_F);
    float2* lut = (float2*)(smemf + OFF_LUT_F);

    const int img = blockIdx.x;
    const float* src;
    float* dstp;
    int dstride;
    if (img < NIMG_OUT) {
        int b = img / 48, rem = img - b * 48;
        int m = rem / 3, c = rem - m * 3;
        src  = outp + (size_t)img * 16384;
        dstp = g_magM + ((b * 3 + c) * NBINS) * 16 + m;   // stride 16 per bin
        dstride = 16;
    } else {
        int bc = img - NIMG_OUT;
        src  = tgt + (size_t)bc * 16384;
        dstp = g_magT + bc * NBINS;
        dstride = 1;
    }

    if (tid < 128) {
        float s, c;
        sincosf(-6.283185307179586f * (float)tid / 128.0f, &s, &c);
        lut[tid] = make_float2(c, s);
    }

    const int warp = tid >> 5, lane = tid & 31;
    const int wg   = warp >> 2;            // chunk within round
    const int kwb  = (warp & 3) * 4;       // 4 kw bins per warp

    #pragma unroll 1
    for (int round = 0; round < 2; round++) {
        __syncthreads();
        // loader: fold x[w] +/- x[w+64] into s/d halves (1024 pair-tasks per round)
        const float4* src4 = (const float4*)src;
        #pragma unroll
        for (int i = 0; i < 4; i++) {
            int e = tid + i * 256;           // 0..1023
            int half = e >> 9, j = e & 511;  // 32 rows x 16 col4-pairs
            int row = j >> 4, c4 = j & 15;
            const float4* rp = src4 + (round * 2 + half) * 1024 + row * 32;
            float4 xa = rp[c4], xb = rp[c4 + 16];
            float* bp = smemf + half * 32 * SX_STRIDE + row * SX_STRIDE;
            *(float4*)(bp + c4 * 4) =
                make_float4(xa.x + xb.x, xa.y + xb.y, xa.z + xb.z, xa.w + xb.w);
            *(float4*)(bp + 64 + c4 * 4) =
                make_float4(xa.x - xb.x, xa.y - xb.y, xa.z - xb.z, xa.w - xb.w);
        }
        __syncthreads();

        const float* myrow = smemf + wg * 32 * SX_STRIDE + lane * SX_STRIDE;
        float aE[4], aO[4];
        #pragma unroll
        for (int i = 0; i < 4; i++) { aE[i] = 0.f; aO[i] = 0.f; }
        // even bins (kwb, kwb+2) over s-half ; odd bins (kwb+1, kwb+3) over d-half
        if      (kwb == 0)  { S1R<0,  2,  0>::run(myrow, aE); S1R<1,  3,  0>::run(myrow + 64, aO); }
        else if (kwb == 4)  { S1R<4,  6,  0>::run(myrow, aE); S1R<5,  7,  0>::run(myrow + 64, aO); }
        else if (kwb == 8)  { S1R<8,  10, 0>::run(myrow, aE); S1R<9,  11, 0>::run(myrow + 64, aO); }
        else                { S1R<12, 14, 0>::run(myrow, aE); S1R<13, 15, 0>::run(myrow + 64, aO); }

        int h = round * 64 + wg * 32 + lane;
        u64* d = syu + h * 17 + kwb;
        d[0] = pack2(aE[0], aE[1]); d[1] = pack2(aO[0], aO[1]);
        d[2] = pack2(aE[2], aE[3]); d[3] = pack2(aO[2], aO[3]);
    }
    __syncthreads();

    // stage 2: thread -> (kw = tid&15, kh in {tid>>4, tid>>4+16}); parity fold h vs h+64
    const int kw  = tid & 15;
    const int kh0 = tid >> 4;
    const int kh1 = kh0 + 16;
    const float sgn = (kh0 & 1) ? -1.f : 1.f;
    const u64 sgn2 = pack2(sgn, sgn);
    u64 U0 = 0, V0 = 0, U1 = 0, V1 = 0;
    #pragma unroll 4
    for (int h = 0; h < 64; h++) {
        u64 ya = syu[h * 17 + kw];
        u64 yb = syu[(h + 64) * 17 + kw];
        u64 y  = fma2(sgn2, yb, ya);           // y[h] +/- y[h+64]
        float yr, yi; unpack2(y, yr, yi);
        u64 yr2 = pack2(yr, yr), yi2 = pack2(yi, yi);
        u64 t0 = *(const u64*)&lut[(kh0 * h) & 127];
        u64 t1 = *(const u64*)&lut[(kh1 * h) & 127];
        U0 = fma2(yr2, t0, U0);
        V0 = fma2(yi2, t0, V0);
        U1 = fma2(yr2, t1, U1);
        V1 = fma2(yi2, t1, V1);
    }
    float u0l, u0h, v0l, v0h, u1l, u1h, v1l, v1h;
    unpack2(U0, u0l, u0h); unpack2(V0, v0l, v0h);
    unpack2(U1, u1l, u1h); unpack2(V1, v1l, v1h);
    float zr0 = u0l - v0h, zi0 = u0h + v0l;
    float zr1 = u1l - v1h, zi1 = u1h + v1l;
    dstp[(kh0 * 16 + kw) * dstride] = sqrtf(zr0 * zr0 + zi0 * zi0);
    dstp[(kh1 * 16 + kw) * dstride] = sqrtf(zr1 * zr1 + zi1 * zi1);
}

// Frequency CRPS + last-block finalize. Member-contiguous layout -> 4x LDG.128 per thread.
__global__ void k_freqfinal(float* out) {
    int tid = threadIdx.x;
    int idx = blockIdx.x * 256 + tid;          // (bc, bin) flat, 0..12287
    float t = g_magT[idx];
    const float4* mp = (const float4*)(g_magM + (size_t)idx * 16);
    float4 q0 = mp[0], q1 = mp[1], q2 = mp[2], q3 = mp[3];
    float p[16] = { q0.x, q0.y, q0.z, q0.w, q1.x, q1.y, q1.z, q1.w,
                    q2.x, q2.y, q2.z, q2.w, q3.x, q3.y, q3.z, q3.w };
    float s1 = 0.f, s2 = 0.f;
    #pragma unroll
    for (int i = 0; i < 16; i++) {
        s1 += fabsf(p[i] - t);
        #pragma unroll
        for (int j = i + 1; j < 16; j++) s2 += fabsf(p[i] - p[j]);
    }
    reduce_and_add(s1, s2, 2);

    __shared__ bool isLast;
    if (tid == 0) {
        __threadfence();
        unsigned prev = atomicAdd(&g_done, 1u);
        isLast = (prev == 47u);
    }
    __syncthreads();
    if (isLast && tid == 0) {
        __threadfence();
        double S1  = g_acc[0], S2p  = g_acc[1];
        double S1f = g_acc[2], S2fp = g_acc[3];
        const double eps = 0.05 / 16.0;
        const double Np  = 8.0 * 16.0 * 3.0 * 16384.0;
        const double Nf  = 8.0 * 16.0 * 3.0 * 8320.0;
        double crps_p = S1  / Np - (1.0 - eps) * S2p  / (15.0 * Np);
        double crps_f = S1f / Nf - (1.0 - eps) * S2fp / (15.0 * Nf);
        out[0] = (float)(crps_p + 0.1 * crps_f);
        g_acc[0] = 0.0; g_acc[1] = 0.0; g_acc[2] = 0.0; g_acc[3] = 0.0;
        __threadfence();
        g_done = 0u;
    }
}

extern "C" void kernel_launch(void* const* d_in, const int* in_sizes, int n_in,
                              void* d_out, int out_size) {
    const float* target = (const float*)d_in[0];
    const float* output = (const float*)d_in[1];
    if (in_sizes[0] > in_sizes[1]) {
        const float* tmp = target; target = output; output = tmp;
    }
    float* out = (float*)d_out;

    static int smem_set = 0;
    if (!smem_set) {
        cudaFuncSetAttribute(k_main, cudaFuncAttributeMaxDynamicSharedMemorySize, SMEM_BYTES);
        smem_set = 1;
    }

    k_main<<<NIMG + NCRPS_BLK, 256, SMEM_BYTES>>>(output, target);
    k_freqfinal<<<48, 256>>>(out);
}